// round 8
// baseline (speedup 1.0000x reference)
#include <cuda_runtime.h>
#include <cstdint>
#include <cstddef>

// ---------------- problem constants ----------------
#define BB 4
#define TT 2048
#define DD 768
#define HH 12
#define HD 64
#define WIN 128
#define QT 64
#define NKM 192

// ---------------- GEMM tiling ----------------
#define MT 128
#define NT 128
#define KC 32
#define KDIM 768
#define NCHUNK (KDIM / KC)
#define GEMM_THREADS 256
#define STR 36
#define TILE_F (128 * STR)
#define NSTAGE 3
#define GEMM_SMEM (NSTAGE * 2 * TILE_F * 4)   // 110592 B -> 2 CTAs/SM

// ---------------- attention smem strides ----------------
#define ASTR 68
#define VSTR 196
#define ATT_F (QT * ASTR + NKM * ASTR + HD * VSTR + QT * VSTR)
#define ATT_SMEM (ATT_F * 4)

// ---------------- device scratch ----------------
__device__ __align__(128) float g_x  [(size_t)BB * TT * DD];
__device__ __align__(128) float g_qkv[(size_t)BB * TT * 3 * DD];
__device__ __align__(128) float g_att[(size_t)BB * TT * DD];
__device__ __align__(128) float g_wqkvT[(size_t)3 * DD * DD];
__device__ __align__(128) float g_woutT[(size_t)DD * DD];

// ---------------- helpers ----------------
__device__ __forceinline__ uint32_t smem_u32(const void* p) {
    uint32_t a;
    asm("{ .reg .u64 t; cvta.to.shared.u64 t, %1; cvt.u32.u64 %0, t; }" : "=r"(a) : "l"(p));
    return a;
}
__device__ __forceinline__ void cpa16(uint32_t s, const void* g) {
    asm volatile("cp.async.cg.shared.global [%0], [%1], 16;" :: "r"(s), "l"(g));
}
__device__ __forceinline__ uint32_t f2tf32(float x) {
    uint32_t r;
    asm("cvt.rna.tf32.f32 %0, %1;" : "=r"(r) : "f"(x));
    return r;
}
__device__ __forceinline__ float rnd_tf32(float x) { return __uint_as_float(f2tf32(x)); }

__device__ __forceinline__ void mma_tf32_16x8x8(float* d, const uint32_t* a, const uint32_t* b) {
    asm volatile(
        "mma.sync.aligned.m16n8k8.row.col.f32.tf32.tf32.f32 "
        "{%0,%1,%2,%3}, {%4,%5,%6,%7}, {%8,%9}, {%0,%1,%2,%3};"
        : "+f"(d[0]), "+f"(d[1]), "+f"(d[2]), "+f"(d[3])
        : "r"(a[0]), "r"(a[1]), "r"(a[2]), "r"(a[3]), "r"(b[0]), "r"(b[1]));
}

// ---------------------------------------------------------------------------
__global__ void __launch_bounds__(256) round_tf32_k(const float* __restrict__ src,
                                                    float* __restrict__ dst, int n4) {
    int i = blockIdx.x * 256 + threadIdx.x;
    if (i < n4) {
        float4 v = reinterpret_cast<const float4*>(src)[i];
        v.x = rnd_tf32(v.x); v.y = rnd_tf32(v.y);
        v.z = rnd_tf32(v.z); v.w = rnd_tf32(v.w);
        reinterpret_cast<float4*>(dst)[i] = v;
    }
}

__global__ void __launch_bounds__(256) transpose_k(const float* __restrict__ src,
                                                   float* __restrict__ dst,
                                                   int R, int C) {
    __shared__ float t[32][33];
    const int c0 = blockIdx.x * 32, r0 = blockIdx.y * 32;
    const int x = threadIdx.x, y = threadIdx.y;
#pragma unroll
    for (int dy = 0; dy < 32; dy += 8)
        t[y + dy][x] = rnd_tf32(src[(size_t)(r0 + y + dy) * C + c0 + x]);
    __syncthreads();
#pragma unroll
    for (int dy = 0; dy < 32; dy += 8)
        dst[(size_t)(c0 + y + dy) * R + r0 + x] = t[x][y + dy];
}

// ---------------------------------------------------------------------------
// tf32 mma.sync GEMM, 3-stage cp.async pipeline, pre-rounded inputs.
// ---------------------------------------------------------------------------
__global__ void __launch_bounds__(GEMM_THREADS, 2) gemm_tf32(const float* __restrict__ A,
                                                             const float* __restrict__ Bt,
                                                             float* __restrict__ C,
                                                             int N, int round_out) {
    extern __shared__ float smf[];
    uint32_t sAu[NSTAGE], sBu[NSTAGE];
    const float* sAf[NSTAGE];
    const float* sBf[NSTAGE];
#pragma unroll
    for (int s = 0; s < NSTAGE; s++) {
        sAf[s] = smf + s * 2 * TILE_F;
        sBf[s] = smf + s * 2 * TILE_F + TILE_F;
        sAu[s] = smem_u32(sAf[s]);
        sBu[s] = smem_u32(sBf[s]);
    }

    const int tid = threadIdx.x;
    const int wid = tid >> 5, lane = tid & 31;
    const int gid = lane >> 2, tg = lane & 3;
    const int wm = (wid & 1) * 64;
    const int wn = (wid >> 1) * 32;
    const int bm = blockIdx.y * MT;
    const int bn = blockIdx.x * NT;

    int lrow[4], lc4[4];
    const float *gA[4], *gB[4];
#pragma unroll
    for (int i = 0; i < 4; i++) {
        int f = tid + i * 256;
        lrow[i] = f >> 3;
        lc4[i]  = f & 7;
        gA[i] = A  + (size_t)(bm + lrow[i]) * KDIM + lc4[i] * 4;
        gB[i] = Bt + (size_t)(bn + lrow[i]) * KDIM + lc4[i] * 4;
    }

    auto load_chunk = [&](int kc, int s) {
        const int ko = kc * KC;
#pragma unroll
        for (int i = 0; i < 4; i++) {
            uint32_t off = (uint32_t)(lrow[i] * STR + lc4[i] * 4) * 4u;
            cpa16(sAu[s] + off, gA[i] + ko);
            cpa16(sBu[s] + off, gB[i] + ko);
        }
        asm volatile("cp.async.commit_group;" ::: "memory");
    };

    float acc[4][4][4];
#pragma unroll
    for (int mi = 0; mi < 4; mi++)
#pragma unroll
        for (int ni = 0; ni < 4; ni++)
#pragma unroll
            for (int q = 0; q < 4; q++) acc[mi][ni][q] = 0.f;

    // Prologue: chunks 0 and 1 in flight.
    load_chunk(0, 0);
    load_chunk(1, 1);

    int sidx = 0;   // stage of chunk c
    for (int c = 0; c < NCHUNK; ++c) {
        // Ensure chunk c has arrived. While a later load is still in flight we
        // can leave exactly one group pending; on the tail, drain fully.
        if (c + 1 < NCHUNK) {
            asm volatile("cp.async.wait_group 1;" ::: "memory");
        } else {
            asm volatile("cp.async.wait_group 0;" ::: "memory");
        }
        __syncthreads();   // also guarantees stage (c+2)%3 is no longer being read

        if (c + 2 < NCHUNK) {
            int s2 = sidx + 2; if (s2 >= NSTAGE) s2 -= NSTAGE;
            load_chunk(c + 2, s2);
        }

        const uint32_t* cA = reinterpret_cast<const uint32_t*>(sAf[sidx]);
        const uint32_t* cB = reinterpret_cast<const uint32_t*>(sBf[sidx]);
#pragma unroll
        for (int k8 = 0; k8 < 4; k8++) {
            const int k0 = k8 * 8;
            uint32_t af[4][4], bf[4][2];
#pragma unroll
            for (int mi = 0; mi < 4; mi++) {
                const int r0 = wm + mi * 16 + gid;
                af[mi][0] = cA[(r0)     * STR + k0 + tg];
                af[mi][1] = cA[(r0 + 8) * STR + k0 + tg];
                af[mi][2] = cA[(r0)     * STR + k0 + tg + 4];
                af[mi][3] = cA[(r0 + 8) * STR + k0 + tg + 4];
            }
#pragma unroll
            for (int ni = 0; ni < 4; ni++) {
                const int n0 = wn + ni * 8 + gid;
                bf[ni][0] = cB[n0 * STR + k0 + tg];
                bf[ni][1] = cB[n0 * STR + k0 + tg + 4];
            }
#pragma unroll
            for (int mi = 0; mi < 4; mi++)
#pragma unroll
                for (int ni = 0; ni < 4; ni++)
                    mma_tf32_16x8x8(acc[mi][ni], af[mi], bf[ni]);
        }
        if (++sidx == NSTAGE) sidx = 0;
    }

#pragma unroll
    for (int mi = 0; mi < 4; mi++) {
        const int r0 = bm + wm + mi * 16 + gid;
#pragma unroll
        for (int ni = 0; ni < 4; ni++) {
            const int c0 = bn + wn + ni * 8 + tg * 2;
            float4 v = make_float4(acc[mi][ni][0], acc[mi][ni][1],
                                   acc[mi][ni][2], acc[mi][ni][3]);
            if (round_out) {
                v.x = rnd_tf32(v.x); v.y = rnd_tf32(v.y);
                v.z = rnd_tf32(v.z); v.w = rnd_tf32(v.w);
            }
            *reinterpret_cast<float2*>(&C[(size_t)r0 * N + c0])       = make_float2(v.x, v.y);
            *reinterpret_cast<float2*>(&C[(size_t)(r0 + 8) * N + c0]) = make_float2(v.z, v.w);
        }
    }
}

// ---------------------------------------------------------------------------
// Tensorized sliding-window attention (unchanged from R7 passing kernel).
// ---------------------------------------------------------------------------
__global__ void __launch_bounds__(256) attn_mma(const float* __restrict__ qkv,
                                                float* __restrict__ att) {
    const int q0 = blockIdx.x * QT;
    const int h  = blockIdx.y;
    const int b  = blockIdx.z;
    const int tid = threadIdx.x;
    const int wid = tid >> 5, lane = tid & 31;
    const int gid = lane >> 2, tg = lane & 3;
    const int mrow  = (wid >> 1) * 16;
    const int nhalf = (wid & 1);

    extern __shared__ float sm[];
    float* sQ  = sm;
    float* sK  = sQ  + QT  * ASTR;
    float* sVt = sK  + NKM * ASTR;
    float* sS  = sVt + HD  * VSTR;

    const int kstart = max(0, q0 - WIN);
    const int nk     = q0 + QT - kstart;
    const int hq     = h * HD;
    const size_t rowbase = (size_t)(b * TT) * (3 * DD);

    for (int idx = tid; idx < QT * (HD / 4); idx += 256) {
        int q = idx >> 4, d4 = (idx & 15) * 4;
        float4 v = *reinterpret_cast<const float4*>(
            &qkv[rowbase + (size_t)(q0 + q) * (3 * DD) + hq + d4]);
        float* dst = &sQ[q * ASTR + d4];
        dst[0] = v.x; dst[1] = v.y; dst[2] = v.z; dst[3] = v.w;
    }
    for (int idx = tid; idx < nk * (HD / 4); idx += 256) {
        int kk = idx >> 4, d4 = (idx & 15) * 4;
        float4 v = *reinterpret_cast<const float4*>(
            &qkv[rowbase + (size_t)(kstart + kk) * (3 * DD) + DD + hq + d4]);
        float* dst = &sK[kk * ASTR + d4];
        dst[0] = v.x; dst[1] = v.y; dst[2] = v.z; dst[3] = v.w;
    }
    for (int idx = tid; idx < HD * VSTR; idx += 256) sVt[idx] = 0.f;
    __syncthreads();
    for (int idx = tid; idx < nk * (HD / 4); idx += 256) {
        int kk = idx >> 4, d4 = (idx & 15) * 4;
        float4 v = *reinterpret_cast<const float4*>(
            &qkv[rowbase + (size_t)(kstart + kk) * (3 * DD) + 2 * DD + hq + d4]);
        sVt[(d4 + 0) * VSTR + kk] = v.x;
        sVt[(d4 + 1) * VSTR + kk] = v.y;
        sVt[(d4 + 2) * VSTR + kk] = v.z;
        sVt[(d4 + 3) * VSTR + kk] = v.w;
    }
    __syncthreads();

    {
        float accS[12][4];
#pragma unroll
        for (int ni = 0; ni < 12; ni++)
#pragma unroll
            for (int q = 0; q < 4; q++) accS[ni][q] = 0.f;

        const int ncol0 = nhalf * 96;
        const int r0 = mrow + gid;
        const uint32_t* uQ = reinterpret_cast<const uint32_t*>(sQ);
        const uint32_t* uK = reinterpret_cast<const uint32_t*>(sK);
#pragma unroll
        for (int k8 = 0; k8 < 8; k8++) {
            const int k0 = k8 * 8;
            uint32_t af[4];
            af[0] = uQ[(r0)     * ASTR + k0 + tg];
            af[1] = uQ[(r0 + 8) * ASTR + k0 + tg];
            af[2] = uQ[(r0)     * ASTR + k0 + tg + 4];
            af[3] = uQ[(r0 + 8) * ASTR + k0 + tg + 4];
#pragma unroll
            for (int ni = 0; ni < 12; ni++) {
                const int n0 = ncol0 + ni * 8 + gid;
                uint32_t bf[2];
                bf[0] = uK[n0 * ASTR + k0 + tg];
                bf[1] = uK[n0 * ASTR + k0 + tg + 4];
                mma_tf32_16x8x8(accS[ni], af, bf);
            }
        }

        const float scale = 0.125f;
#pragma unroll
        for (int ni = 0; ni < 12; ni++) {
            const int col = ncol0 + ni * 8 + 2 * tg;
            const int r   = mrow + gid;
            const int i0 = q0 + r, i1 = i0 + 8;
            const int j0 = kstart + col, j1 = j0 + 1;
            sS[(r)     * VSTR + col]     = (j0 <= i0 && j0 >= i0 - WIN) ? accS[ni][0] * scale : -1e30f;
            sS[(r)     * VSTR + col + 1] = (j1 <= i0 && j1 >= i0 - WIN) ? accS[ni][1] * scale : -1e30f;
            sS[(r + 8) * VSTR + col]     = (j0 <= i1 && j0 >= i1 - WIN) ? accS[ni][2] * scale : -1e30f;
            sS[(r + 8) * VSTR + col + 1] = (j1 <= i1 && j1 >= i1 - WIN) ? accS[ni][3] * scale : -1e30f;
        }
    }
    __syncthreads();

    for (int q = wid; q < QT; q += 8) {
        float* row = &sS[q * VSTR];
        float m = -1e30f;
#pragma unroll
        for (int kk = lane; kk < NKM; kk += 32) m = fmaxf(m, row[kk]);
#pragma unroll
        for (int o = 16; o; o >>= 1) m = fmaxf(m, __shfl_xor_sync(0xffffffffu, m, o));
        float s = 0.f;
        float ev[6];
#pragma unroll
        for (int t = 0; t < 6; t++) {
            float e = __expf(row[lane + t * 32] - m);
            ev[t] = e;
            s += e;
        }
#pragma unroll
        for (int o = 16; o; o >>= 1) s += __shfl_xor_sync(0xffffffffu, s, o);
        float inv = 1.f / s;
#pragma unroll
        for (int t = 0; t < 6; t++) row[lane + t * 32] = rnd_tf32(ev[t] * inv);
    }
    __syncthreads();

    {
        float accO[4][4];
#pragma unroll
        for (int ni = 0; ni < 4; ni++)
#pragma unroll
            for (int q = 0; q < 4; q++) accO[ni][q] = 0.f;

        const int dcol0 = nhalf * 32;
        const int r0 = mrow + gid;
        const uint32_t* uS = reinterpret_cast<const uint32_t*>(sS);
        const uint32_t* uV = reinterpret_cast<const uint32_t*>(sVt);
#pragma unroll
        for (int ks = 0; ks < 24; ks++) {
            const int k0 = ks * 8;
            uint32_t af[4];
            af[0] = uS[(r0)     * VSTR + k0 + tg];
            af[1] = uS[(r0 + 8) * VSTR + k0 + tg];
            af[2] = uS[(r0)     * VSTR + k0 + tg + 4];
            af[3] = uS[(r0 + 8) * VSTR + k0 + tg + 4];
#pragma unroll
            for (int ni = 0; ni < 4; ni++) {
                const int n0 = dcol0 + ni * 8 + gid;
                uint32_t bf[2];
                bf[0] = uV[n0 * VSTR + k0 + tg];
                bf[1] = uV[n0 * VSTR + k0 + tg + 4];
                mma_tf32_16x8x8(accO[ni], af, bf);
            }
        }

#pragma unroll
        for (int ni = 0; ni < 4; ni++) {
            const int dc = dcol0 + ni * 8 + 2 * tg;
            const int r  = mrow + gid;
            float2 v0 = make_float2(rnd_tf32(accO[ni][0]), rnd_tf32(accO[ni][1]));
            float2 v1 = make_float2(rnd_tf32(accO[ni][2]), rnd_tf32(accO[ni][3]));
            *reinterpret_cast<float2*>(&att[(size_t)(b * TT + q0 + r)     * DD + hq + dc]) = v0;
            *reinterpret_cast<float2*>(&att[(size_t)(b * TT + q0 + r + 8) * DD + hq + dc]) = v1;
        }
    }
}

// ---------------------------------------------------------------------------
extern "C" void kernel_launch(void* const* d_in, const int* in_sizes, int n_in,
                              void* d_out, int out_size) {
    const float* x    = (const float*)d_in[0];
    const float* Wqkv = (const float*)d_in[1];
    const float* Wout = (const float*)d_in[2];
    float* out = (float*)d_out;

    float *xr, *qkv, *att, *wqkvT, *woutT;
    cudaGetSymbolAddress((void**)&xr, g_x);
    cudaGetSymbolAddress((void**)&qkv, g_qkv);
    cudaGetSymbolAddress((void**)&att, g_att);
    cudaGetSymbolAddress((void**)&wqkvT, g_wqkvT);
    cudaGetSymbolAddress((void**)&woutT, g_woutT);

    cudaFuncSetAttribute(attn_mma, cudaFuncAttributeMaxDynamicSharedMemorySize, ATT_SMEM);
    cudaFuncSetAttribute(gemm_tf32, cudaFuncAttributeMaxDynamicSharedMemorySize, GEMM_SMEM);

    const int M = BB * TT;
    const int xn4 = M * DD / 4;

    round_tf32_k<<<(xn4 + 255) / 256, 256>>>(x, xr, xn4);
    transpose_k<<<dim3(3 * DD / 32, DD / 32), dim3(32, 8)>>>(Wqkv, wqkvT, DD, 3 * DD);
    transpose_k<<<dim3(DD / 32, DD / 32), dim3(32, 8)>>>(Wout, woutT, DD, DD);

    gemm_tf32<<<dim3(3 * DD / NT, M / MT), GEMM_THREADS, GEMM_SMEM>>>(xr, wqkvT, qkv, 3 * DD, 1);

    attn_mma<<<dim3(TT / QT, HH, BB), 256, ATT_SMEM>>>(qkv, att);

    gemm_tf32<<<dim3(DD / NT, M / MT), GEMM_THREADS, GEMM_SMEM>>>(att, woutT, out, DD, 0);
}

// round 9
// speedup vs baseline: 1.6526x; 1.6526x over previous
#include <cuda_runtime.h>
#include <cuda_fp16.h>
#include <cstdint>
#include <cstddef>

// ---------------- problem constants ----------------
#define BB 4
#define TT 2048
#define DD 768
#define HH 12
#define HD 64
#define WIN 128
#define QT 64
#define NKM 192

// ---------------- GEMM tiling (fp16) ----------------
#define MT 128
#define NT 128
#define KC 64                  // K chunk in halfs (=128B rows)
#define KDIM 768
#define NCHUNK (KDIM / KC)     // 12
#define GEMM_THREADS 256
#define STRH 72                // smem row stride in halfs (word-stride 36 ≡ 4 mod 32)
#define TILE_H (128 * STRH)    // halfs per tile buffer
#define GEMM_SMEM (2 * 2 * TILE_H * 2)   // 73728 B -> 2 CTAs/SM

// ---------------- attention smem ----------------
#define SQH 72                 // Q/K half stride
#define SVH 200                // Vt/P half stride (word-stride 100 ≡ 4 mod 32)
#define VSTR 196               // score (fp32) stride
// halfs: Q 64*72 + K 192*72 + Vt 64*200 + P 64*200 = 44032 -> 88064 B, then S fp32
#define ATT_SMEM (88064 + QT * VSTR * 4)   // 138240 B

// ---------------- device scratch ----------------
__device__ __align__(128) __half g_x16 [(size_t)BB * TT * DD];
__device__ __align__(128) __half g_qkv [(size_t)BB * TT * 3 * DD];
__device__ __align__(128) __half g_att [(size_t)BB * TT * DD];
__device__ __align__(128) __half g_wqkvT[(size_t)3 * DD * DD];
__device__ __align__(128) __half g_woutT[(size_t)DD * DD];

// ---------------- helpers ----------------
__device__ __forceinline__ uint32_t smem_u32(const void* p) {
    uint32_t a;
    asm("{ .reg .u64 t; cvta.to.shared.u64 t, %1; cvt.u32.u64 %0, t; }" : "=r"(a) : "l"(p));
    return a;
}
__device__ __forceinline__ void cpa16(uint32_t s, const void* g) {
    asm volatile("cp.async.cg.shared.global [%0], [%1], 16;" :: "r"(s), "l"(g));
}
__device__ __forceinline__ void mma_f16_16x8x16(float* d, const uint32_t* a, const uint32_t* b) {
    asm volatile(
        "mma.sync.aligned.m16n8k16.row.col.f32.f16.f16.f32 "
        "{%0,%1,%2,%3}, {%4,%5,%6,%7}, {%8,%9}, {%0,%1,%2,%3};"
        : "+f"(d[0]), "+f"(d[1]), "+f"(d[2]), "+f"(d[3])
        : "r"(a[0]), "r"(a[1]), "r"(a[2]), "r"(a[3]), "r"(b[0]), "r"(b[1]));
}

// ---------------------------------------------------------------------------
// f32 -> f16 elementwise (pairs).
// ---------------------------------------------------------------------------
__global__ void __launch_bounds__(256) f32_to_f16_k(const float* __restrict__ src,
                                                    __half* __restrict__ dst, int n2) {
    int i = blockIdx.x * 256 + threadIdx.x;
    if (i < n2) {
        float2 v = reinterpret_cast<const float2*>(src)[i];
        reinterpret_cast<__half2*>(dst)[i] = __floats2half2_rn(v.x, v.y);
    }
}

// ---------------------------------------------------------------------------
// 32x32 transpose + f16 convert: dst[c][r] = f16(src[r][c]).
// ---------------------------------------------------------------------------
__global__ void __launch_bounds__(256) transpose_f16_k(const float* __restrict__ src,
                                                       __half* __restrict__ dst,
                                                       int R, int C) {
    __shared__ float t[32][33];
    const int c0 = blockIdx.x * 32, r0 = blockIdx.y * 32;
    const int x = threadIdx.x, y = threadIdx.y;
#pragma unroll
    for (int dy = 0; dy < 32; dy += 8)
        t[y + dy][x] = src[(size_t)(r0 + y + dy) * C + c0 + x];
    __syncthreads();
#pragma unroll
    for (int dy = 0; dy < 32; dy += 8)
        dst[(size_t)(c0 + y + dy) * R + r0 + x] = __float2half_rn(t[x][y + dy]);
}

// ---------------------------------------------------------------------------
// fp16 mma.sync GEMM: C[M,N] = A[M,768] * Bt[N,768]^T, A/Bt fp16 K-major.
// CTA 128x128, K-chunk 64 halfs, 2-stage cp.async, 8 warps (2M x 4N).
// out_half: write C as __half (intermediates) else float (final output).
// ---------------------------------------------------------------------------
__global__ void __launch_bounds__(GEMM_THREADS, 2) gemm_f16(const __half* __restrict__ A,
                                                            const __half* __restrict__ Bt,
                                                            void* __restrict__ Cv,
                                                            int N, int out_half) {
    extern __shared__ __half smh[];
    const __half* sA[2] = { smh,          smh + 2 * TILE_H };
    const __half* sB[2] = { smh + TILE_H, smh + 3 * TILE_H };
    const uint32_t sAu[2] = { smem_u32(sA[0]), smem_u32(sA[1]) };
    const uint32_t sBu[2] = { smem_u32(sB[0]), smem_u32(sB[1]) };

    const int tid = threadIdx.x;
    const int wid = tid >> 5, lane = tid & 31;
    const int gid = lane >> 2, tg = lane & 3;
    const int wm = (wid & 1) * 64;
    const int wn = (wid >> 1) * 32;
    const int bm = blockIdx.y * MT;
    const int bn = blockIdx.x * NT;

    // Loader slots: chunk = 128 rows x 64 halfs = 1024 x 16B; 4 per thread per tile.
    int lrow[4], lc8[4];
    const __half *gA[4], *gB[4];
#pragma unroll
    for (int i = 0; i < 4; i++) {
        int f = tid + i * 256;
        lrow[i] = f >> 3;          // 0..127
        lc8[i]  = f & 7;           // 8-half group within 64-half row
        gA[i] = A  + (size_t)(bm + lrow[i]) * KDIM + lc8[i] * 8;
        gB[i] = Bt + (size_t)(bn + lrow[i]) * KDIM + lc8[i] * 8;
    }

    auto load_chunk = [&](int kc, int s) {
        const int ko = kc * KC;
#pragma unroll
        for (int i = 0; i < 4; i++) {
            uint32_t off = (uint32_t)(lrow[i] * STRH + lc8[i] * 8) * 2u;
            cpa16(sAu[s] + off, gA[i] + ko);
            cpa16(sBu[s] + off, gB[i] + ko);
        }
        asm volatile("cp.async.commit_group;" ::: "memory");
    };

    float acc[4][4][4];
#pragma unroll
    for (int mi = 0; mi < 4; mi++)
#pragma unroll
        for (int ni = 0; ni < 4; ni++)
#pragma unroll
            for (int q = 0; q < 4; q++) acc[mi][ni][q] = 0.f;

    load_chunk(0, 0);

    for (int c = 0; c < NCHUNK; ++c) {
        const int s = c & 1;
        if (c + 1 < NCHUNK) {
            load_chunk(c + 1, s ^ 1);
            asm volatile("cp.async.wait_group 1;" ::: "memory");
        } else {
            asm volatile("cp.async.wait_group 0;" ::: "memory");
        }
        __syncthreads();

        const uint32_t* cA = reinterpret_cast<const uint32_t*>(sA[s]);
        const uint32_t* cB = reinterpret_cast<const uint32_t*>(sB[s]);
#pragma unroll
        for (int k16 = 0; k16 < 4; k16++) {
            const int kw = k16 * 8;        // word offset of this 16-half K step
            uint32_t af[4][4], bf[4][2];
#pragma unroll
            for (int mi = 0; mi < 4; mi++) {
                const int r0 = wm + mi * 16 + gid;
                af[mi][0] = cA[(r0)     * 36 + kw + tg];
                af[mi][1] = cA[(r0 + 8) * 36 + kw + tg];
                af[mi][2] = cA[(r0)     * 36 + kw + tg + 4];
                af[mi][3] = cA[(r0 + 8) * 36 + kw + tg + 4];
            }
#pragma unroll
            for (int ni = 0; ni < 4; ni++) {
                const int n0 = wn + ni * 8 + gid;
                bf[ni][0] = cB[n0 * 36 + kw + tg];
                bf[ni][1] = cB[n0 * 36 + kw + tg + 4];
            }
#pragma unroll
            for (int mi = 0; mi < 4; mi++)
#pragma unroll
                for (int ni = 0; ni < 4; ni++)
                    mma_f16_16x8x16(acc[mi][ni], af[mi], bf[ni]);
        }
        __syncthreads();
    }

#pragma unroll
    for (int mi = 0; mi < 4; mi++) {
        const int r0 = bm + wm + mi * 16 + gid;
#pragma unroll
        for (int ni = 0; ni < 4; ni++) {
            const int c0 = bn + wn + ni * 8 + tg * 2;
            if (out_half) {
                __half* Ch = (__half*)Cv;
                *reinterpret_cast<__half2*>(&Ch[(size_t)r0 * N + c0]) =
                    __floats2half2_rn(acc[mi][ni][0], acc[mi][ni][1]);
                *reinterpret_cast<__half2*>(&Ch[(size_t)(r0 + 8) * N + c0]) =
                    __floats2half2_rn(acc[mi][ni][2], acc[mi][ni][3]);
            } else {
                float* Cf = (float*)Cv;
                *reinterpret_cast<float2*>(&Cf[(size_t)r0 * N + c0]) =
                    make_float2(acc[mi][ni][0], acc[mi][ni][1]);
                *reinterpret_cast<float2*>(&Cf[(size_t)(r0 + 8) * N + c0]) =
                    make_float2(acc[mi][ni][2], acc[mi][ni][3]);
            }
        }
    }
}

// ---------------------------------------------------------------------------
// fp16 tensorized sliding-window attention.
// ---------------------------------------------------------------------------
__global__ void __launch_bounds__(256) attn_mma(const __half* __restrict__ qkv,
                                                __half* __restrict__ att) {
    const int q0 = blockIdx.x * QT;
    const int h  = blockIdx.y;
    const int b  = blockIdx.z;
    const int tid = threadIdx.x;
    const int wid = tid >> 5, lane = tid & 31;
    const int gid = lane >> 2, tg = lane & 3;
    const int mrow  = (wid >> 1) * 16;
    const int nhalf = (wid & 1);

    extern __shared__ __half smh[];
    __half* sQ  = smh;                       // [64][SQH]
    __half* sK  = sQ  + QT  * SQH;           // [192][SQH]
    __half* sVt = sK  + NKM * SQH;           // [64][SVH]  V transposed [d][kk]
    __half* sP  = sVt + HD  * SVH;           // [64][SVH]  probabilities
    float*  sS  = reinterpret_cast<float*>(sP + QT * SVH);   // [64][VSTR] scores

    const int kstart = max(0, q0 - WIN);
    const int nk     = q0 + QT - kstart;
    const int hq     = h * HD;
    const size_t rowbase = (size_t)(b * TT) * (3 * DD);

    // Q: 64 rows x 64 halfs, 8 halfs per op
    for (int idx = tid; idx < QT * (HD / 8); idx += 256) {
        int q = idx >> 3, d8 = (idx & 7) * 8;
        uint4 v = *reinterpret_cast<const uint4*>(
            &qkv[rowbase + (size_t)(q0 + q) * (3 * DD) + hq + d8]);
        *reinterpret_cast<uint4*>(&sQ[q * SQH + d8]) = v;
    }
    // K
    for (int idx = tid; idx < nk * (HD / 8); idx += 256) {
        int kk = idx >> 3, d8 = (idx & 7) * 8;
        uint4 v = *reinterpret_cast<const uint4*>(
            &qkv[rowbase + (size_t)(kstart + kk) * (3 * DD) + DD + hq + d8]);
        *reinterpret_cast<uint4*>(&sK[kk * SQH + d8]) = v;
    }
    // Vt zero-fill then transpose-scatter
    for (int idx = tid; idx < HD * SVH / 2; idx += 256)
        reinterpret_cast<uint32_t*>(sVt)[idx] = 0u;
    __syncthreads();
    for (int idx = tid; idx < nk * (HD / 8); idx += 256) {
        int kk = idx >> 3, d8 = (idx & 7) * 8;
        uint4 v = *reinterpret_cast<const uint4*>(
            &qkv[rowbase + (size_t)(kstart + kk) * (3 * DD) + 2 * DD + hq + d8]);
        const __half* hv = reinterpret_cast<const __half*>(&v);
#pragma unroll
        for (int j = 0; j < 8; j++) sVt[(d8 + j) * SVH + kk] = hv[j];
    }
    __syncthreads();

    // ---- QK^T: 12 n-frags x 4 k16 steps ----
    {
        float accS[12][4];
#pragma unroll
        for (int ni = 0; ni < 12; ni++)
#pragma unroll
            for (int q = 0; q < 4; q++) accS[ni][q] = 0.f;

        const int ncol0 = nhalf * 96;
        const int r0 = mrow + gid;
        const uint32_t* uQ = reinterpret_cast<const uint32_t*>(sQ);
        const uint32_t* uK = reinterpret_cast<const uint32_t*>(sK);
#pragma unroll
        for (int k16 = 0; k16 < 4; k16++) {
            const int kw = k16 * 8;
            uint32_t af[4];
            af[0] = uQ[(r0)     * 36 + kw + tg];
            af[1] = uQ[(r0 + 8) * 36 + kw + tg];
            af[2] = uQ[(r0)     * 36 + kw + tg + 4];
            af[3] = uQ[(r0 + 8) * 36 + kw + tg + 4];
#pragma unroll
            for (int ni = 0; ni < 12; ni++) {
                const int n0 = ncol0 + ni * 8 + gid;
                uint32_t bf[2];
                bf[0] = uK[n0 * 36 + kw + tg];
                bf[1] = uK[n0 * 36 + kw + tg + 4];
                mma_f16_16x8x16(accS[ni], af, bf);
            }
        }

        const float scale = 0.125f;
#pragma unroll
        for (int ni = 0; ni < 12; ni++) {
            const int col = ncol0 + ni * 8 + 2 * tg;
            const int r   = mrow + gid;
            const int i0 = q0 + r, i1 = i0 + 8;
            const int j0 = kstart + col, j1 = j0 + 1;
            sS[(r)     * VSTR + col]     = (j0 <= i0 && j0 >= i0 - WIN) ? accS[ni][0] * scale : -1e30f;
            sS[(r)     * VSTR + col + 1] = (j1 <= i0 && j1 >= i0 - WIN) ? accS[ni][1] * scale : -1e30f;
            sS[(r + 8) * VSTR + col]     = (j0 <= i1 && j0 >= i1 - WIN) ? accS[ni][2] * scale : -1e30f;
            sS[(r + 8) * VSTR + col + 1] = (j1 <= i1 && j1 >= i1 - WIN) ? accS[ni][3] * scale : -1e30f;
        }
    }
    __syncthreads();

    // ---- softmax (fp32 scores -> fp16 probs) ----
    for (int q = wid; q < QT; q += 8) {
        const float* row = &sS[q * VSTR];
        float m = -1e30f;
#pragma unroll
        for (int t = 0; t < 6; t++) m = fmaxf(m, row[lane + t * 32]);
#pragma unroll
        for (int o = 16; o; o >>= 1) m = fmaxf(m, __shfl_xor_sync(0xffffffffu, m, o));
        float s = 0.f;
        float ev[6];
#pragma unroll
        for (int t = 0; t < 6; t++) {
            float e = __expf(row[lane + t * 32] - m);
            ev[t] = e;
            s += e;
        }
#pragma unroll
        for (int o = 16; o; o >>= 1) s += __shfl_xor_sync(0xffffffffu, s, o);
        float inv = 1.f / s;
        __half* prow = &sP[q * SVH];
#pragma unroll
        for (int t = 0; t < 6; t++) prow[lane + t * 32] = __float2half_rn(ev[t] * inv);
    }
    __syncthreads();

    // ---- PV: 4 n-frags x 12 k16 steps ----
    {
        float accO[4][4];
#pragma unroll
        for (int ni = 0; ni < 4; ni++)
#pragma unroll
            for (int q = 0; q < 4; q++) accO[ni][q] = 0.f;

        const int dcol0 = nhalf * 32;
        const int r0 = mrow + gid;
        const uint32_t* uP = reinterpret_cast<const uint32_t*>(sP);
        const uint32_t* uV = reinterpret_cast<const uint32_t*>(sVt);
#pragma unroll
        for (int k16 = 0; k16 < 12; k16++) {
            const int kw = k16 * 8;
            uint32_t af[4];
            af[0] = uP[(r0)     * 100 + kw + tg];
            af[1] = uP[(r0 + 8) * 100 + kw + tg];
            af[2] = uP[(r0)     * 100 + kw + tg + 4];
            af[3] = uP[(r0 + 8) * 100 + kw + tg + 4];
#pragma unroll
            for (int ni = 0; ni < 4; ni++) {
                const int n0 = dcol0 + ni * 8 + gid;
                uint32_t bf[2];
                bf[0] = uV[n0 * 100 + kw + tg];
                bf[1] = uV[n0 * 100 + kw + tg + 4];
                mma_f16_16x8x16(accO[ni], af, bf);
            }
        }

#pragma unroll
        for (int ni = 0; ni < 4; ni++) {
            const int dc = dcol0 + ni * 8 + 2 * tg;
            const int r  = mrow + gid;
            *reinterpret_cast<__half2*>(&att[(size_t)(b * TT + q0 + r) * DD + hq + dc]) =
                __floats2half2_rn(accO[ni][0], accO[ni][1]);
            *reinterpret_cast<__half2*>(&att[(size_t)(b * TT + q0 + r + 8) * DD + hq + dc]) =
                __floats2half2_rn(accO[ni][2], accO[ni][3]);
        }
    }
}

// ---------------------------------------------------------------------------
extern "C" void kernel_launch(void* const* d_in, const int* in_sizes, int n_in,
                              void* d_out, int out_size) {
    const float* x    = (const float*)d_in[0];
    const float* Wqkv = (const float*)d_in[1];
    const float* Wout = (const float*)d_in[2];
    float* out = (float*)d_out;

    __half *x16, *qkv, *att, *wqkvT, *woutT;
    cudaGetSymbolAddress((void**)&x16, g_x16);
    cudaGetSymbolAddress((void**)&qkv, g_qkv);
    cudaGetSymbolAddress((void**)&att, g_att);
    cudaGetSymbolAddress((void**)&wqkvT, g_wqkvT);
    cudaGetSymbolAddress((void**)&woutT, g_woutT);

    cudaFuncSetAttribute(attn_mma, cudaFuncAttributeMaxDynamicSharedMemorySize, ATT_SMEM);
    cudaFuncSetAttribute(gemm_f16, cudaFuncAttributeMaxDynamicSharedMemorySize, GEMM_SMEM);

    const int M = BB * TT;
    const int xn2 = M * DD / 2;

    // 0) convert x to fp16; transpose+convert weights
    f32_to_f16_k<<<(xn2 + 255) / 256, 256>>>(x, x16, xn2);
    transpose_f16_k<<<dim3(3 * DD / 32, DD / 32), dim3(32, 8)>>>(Wqkv, wqkvT, DD, 3 * DD);
    transpose_f16_k<<<dim3(DD / 32, DD / 32), dim3(32, 8)>>>(Wout, woutT, DD, DD);

    // 1) QKV projection (fp16 in/out)
    gemm_f16<<<dim3(3 * DD / NT, M / MT), GEMM_THREADS, GEMM_SMEM>>>(x16, wqkvT, qkv, 3 * DD, 1);

    // 2) attention (fp16 in/out, fp32 scores)
    attn_mma<<<dim3(TT / QT, HH, BB), 256, ATT_SMEM>>>(qkv, att);

    // 3) output projection (fp16 in, fp32 out)
    gemm_f16<<<dim3(DD / NT, M / MT), GEMM_THREADS, GEMM_SMEM>>>(att, woutT, out, DD, 0);
}

// round 10
// speedup vs baseline: 1.9014x; 1.1506x over previous
#include <cuda_runtime.h>
#include <cuda_fp16.h>
#include <cstdint>
#include <cstddef>

// ---------------- problem constants ----------------
#define BB 4
#define TT 2048
#define DD 768
#define HH 12
#define HD 64
#define WIN 128
#define QT 64
#define NKM 192

// ---------------- GEMM tiling (fp16) ----------------
#define MT 128
#define NT 128
#define KC 64                  // K chunk in halfs
#define KDIM 768
#define NCHUNK (KDIM / KC)     // 12
#define GEMM_THREADS 256
#define STRH 72                // smem row stride in halfs (36 words ≡ 4 mod 32)
#define TILE_H (128 * STRH)
#define GEMM_SMEM (2 * 2 * TILE_H * 2)   // 73728 B -> 2 CTAs/SM

// ---------------- attention smem ----------------
#define SQH 72
#define SVH 200                // 100 words ≡ 4 mod 32
#define VSTR 196
#define ATT_SMEM (88064 + QT * VSTR * 4)   // 138240 B

// ---------------- device scratch ----------------
__device__ __align__(128) __half g_x16 [(size_t)BB * TT * DD];
__device__ __align__(128) __half g_qkv [(size_t)BB * TT * 3 * DD];
__device__ __align__(128) __half g_att [(size_t)BB * TT * DD];
__device__ __align__(128) __half g_wqkvT[(size_t)3 * DD * DD];
__device__ __align__(128) __half g_woutT[(size_t)DD * DD];

// ---------------- helpers ----------------
__device__ __forceinline__ uint32_t smem_u32(const void* p) {
    uint32_t a;
    asm("{ .reg .u64 t; cvta.to.shared.u64 t, %1; cvt.u32.u64 %0, t; }" : "=r"(a) : "l"(p));
    return a;
}
__device__ __forceinline__ void cpa16(uint32_t s, const void* g) {
    asm volatile("cp.async.cg.shared.global [%0], [%1], 16;" :: "r"(s), "l"(g));
}
__device__ __forceinline__ void ldsm_x4(uint32_t* r, uint32_t addr) {
    asm volatile("ldmatrix.sync.aligned.m8n8.x4.shared.b16 {%0,%1,%2,%3}, [%4];"
        : "=r"(r[0]), "=r"(r[1]), "=r"(r[2]), "=r"(r[3]) : "r"(addr));
}
__device__ __forceinline__ void mma_f16_16x8x16(float* d, const uint32_t* a, const uint32_t* b) {
    asm volatile(
        "mma.sync.aligned.m16n8k16.row.col.f32.f16.f16.f32 "
        "{%0,%1,%2,%3}, {%4,%5,%6,%7}, {%8,%9}, {%0,%1,%2,%3};"
        : "+f"(d[0]), "+f"(d[1]), "+f"(d[2]), "+f"(d[3])
        : "r"(a[0]), "r"(a[1]), "r"(a[2]), "r"(a[3]), "r"(b[0]), "r"(b[1]));
}

// ---------------------------------------------------------------------------
__global__ void __launch_bounds__(256) f32_to_f16_k(const float* __restrict__ src,
                                                    __half* __restrict__ dst, int n2) {
    int i = blockIdx.x * 256 + threadIdx.x;
    if (i < n2) {
        float2 v = reinterpret_cast<const float2*>(src)[i];
        reinterpret_cast<__half2*>(dst)[i] = __floats2half2_rn(v.x, v.y);
    }
}

__global__ void __launch_bounds__(256) transpose_f16_k(const float* __restrict__ src,
                                                       __half* __restrict__ dst,
                                                       int R, int C) {
    __shared__ float t[32][33];
    const int c0 = blockIdx.x * 32, r0 = blockIdx.y * 32;
    const int x = threadIdx.x, y = threadIdx.y;
#pragma unroll
    for (int dy = 0; dy < 32; dy += 8)
        t[y + dy][x] = src[(size_t)(r0 + y + dy) * C + c0 + x];
    __syncthreads();
#pragma unroll
    for (int dy = 0; dy < 32; dy += 8)
        dst[(size_t)(c0 + y + dy) * R + r0 + x] = __float2half_rn(t[x][y + dy]);
}

// ---------------------------------------------------------------------------
// fp16 mma.sync GEMM with ldmatrix fragment loads.
// ---------------------------------------------------------------------------
__global__ void __launch_bounds__(GEMM_THREADS, 2) gemm_f16(const __half* __restrict__ A,
                                                            const __half* __restrict__ Bt,
                                                            void* __restrict__ Cv,
                                                            int N, int out_half) {
    extern __shared__ __half smh[];
    const uint32_t sAu[2] = { smem_u32(smh),          smem_u32(smh + 2 * TILE_H) };
    const uint32_t sBu[2] = { smem_u32(smh + TILE_H), smem_u32(smh + 3 * TILE_H) };

    const int tid = threadIdx.x;
    const int wid = tid >> 5, lane = tid & 31;
    const int gid = lane >> 2, tg = lane & 3;
    const int wm = (wid & 1) * 64;
    const int wn = (wid >> 1) * 32;
    const int bm = blockIdx.y * MT;
    const int bn = blockIdx.x * NT;

    // ldmatrix per-lane byte offsets (relative to tile base)
    //  A x4: r0..r3 = [m0-7@k0, m8-15@k0, m0-7@k8, m8-15@k8]
    const uint32_t aoff = (uint32_t)((wm + (lane & 7) + ((lane >> 3) & 1) * 8) * STRH
                                     + (lane >> 4) * 8) * 2u;
    //  B x4: r0..r3 = [n0-7@k0, n0-7@k8, n8-15@k0, n8-15@k8]  (two ni per LDSM)
    const uint32_t boff = (uint32_t)((wn + (lane & 7) + ((lane >> 4) & 1) * 8) * STRH
                                     + ((lane >> 3) & 1) * 8) * 2u;
    const uint32_t AMI = 16 * STRH * 2;   // +16 rows
    const uint32_t BNI = 16 * STRH * 2;

    int lrow[4], lc8[4];
    const __half *gA[4], *gB[4];
#pragma unroll
    for (int i = 0; i < 4; i++) {
        int f = tid + i * 256;
        lrow[i] = f >> 3;
        lc8[i]  = f & 7;
        gA[i] = A  + (size_t)(bm + lrow[i]) * KDIM + lc8[i] * 8;
        gB[i] = Bt + (size_t)(bn + lrow[i]) * KDIM + lc8[i] * 8;
    }

    auto load_chunk = [&](int kc, int s) {
        const int ko = kc * KC;
#pragma unroll
        for (int i = 0; i < 4; i++) {
            uint32_t off = (uint32_t)(lrow[i] * STRH + lc8[i] * 8) * 2u;
            cpa16(sAu[s] + off, gA[i] + ko);
            cpa16(sBu[s] + off, gB[i] + ko);
        }
        asm volatile("cp.async.commit_group;" ::: "memory");
    };

    float acc[4][4][4];
#pragma unroll
    for (int mi = 0; mi < 4; mi++)
#pragma unroll
        for (int ni = 0; ni < 4; ni++)
#pragma unroll
            for (int q = 0; q < 4; q++) acc[mi][ni][q] = 0.f;

    load_chunk(0, 0);

    for (int c = 0; c < NCHUNK; ++c) {
        const int s = c & 1;
        if (c + 1 < NCHUNK) {
            load_chunk(c + 1, s ^ 1);
            asm volatile("cp.async.wait_group 1;" ::: "memory");
        } else {
            asm volatile("cp.async.wait_group 0;" ::: "memory");
        }
        __syncthreads();

        const uint32_t abase = sAu[s] + aoff;
        const uint32_t bbase = sBu[s] + boff;
#pragma unroll
        for (int k16 = 0; k16 < 4; k16++) {
            uint32_t af[4][4], bq[2][4];
#pragma unroll
            for (int mi = 0; mi < 4; mi++)
                ldsm_x4(af[mi], abase + mi * AMI + k16 * 32);
#pragma unroll
            for (int nip = 0; nip < 2; nip++)
                ldsm_x4(bq[nip], bbase + nip * BNI + k16 * 32);
#pragma unroll
            for (int mi = 0; mi < 4; mi++)
#pragma unroll
                for (int ni = 0; ni < 4; ni++)
                    mma_f16_16x8x16(acc[mi][ni], af[mi], &bq[ni >> 1][(ni & 1) * 2]);
        }
        __syncthreads();
    }

#pragma unroll
    for (int mi = 0; mi < 4; mi++) {
        const int r0 = bm + wm + mi * 16 + gid;
#pragma unroll
        for (int ni = 0; ni < 4; ni++) {
            const int c0 = bn + wn + ni * 8 + tg * 2;
            if (out_half) {
                __half* Ch = (__half*)Cv;
                *reinterpret_cast<__half2*>(&Ch[(size_t)r0 * N + c0]) =
                    __floats2half2_rn(acc[mi][ni][0], acc[mi][ni][1]);
                *reinterpret_cast<__half2*>(&Ch[(size_t)(r0 + 8) * N + c0]) =
                    __floats2half2_rn(acc[mi][ni][2], acc[mi][ni][3]);
            } else {
                float* Cf = (float*)Cv;
                *reinterpret_cast<float2*>(&Cf[(size_t)r0 * N + c0]) =
                    make_float2(acc[mi][ni][0], acc[mi][ni][1]);
                *reinterpret_cast<float2*>(&Cf[(size_t)(r0 + 8) * N + c0]) =
                    make_float2(acc[mi][ni][2], acc[mi][ni][3]);
            }
        }
    }
}

// ---------------------------------------------------------------------------
// fp16 tensorized sliding-window attention with ldmatrix fragment loads.
// ---------------------------------------------------------------------------
__global__ void __launch_bounds__(256) attn_mma(const __half* __restrict__ qkv,
                                                __half* __restrict__ att) {
    const int q0 = blockIdx.x * QT;
    const int h  = blockIdx.y;
    const int b  = blockIdx.z;
    const int tid = threadIdx.x;
    const int wid = tid >> 5, lane = tid & 31;
    const int gid = lane >> 2, tg = lane & 3;
    const int mrow  = (wid >> 1) * 16;
    const int nhalf = (wid & 1);

    extern __shared__ __half smh[];
    __half* sQ  = smh;
    __half* sK  = sQ  + QT  * SQH;
    __half* sVt = sK  + NKM * SQH;
    __half* sP  = sVt + HD  * SVH;
    float*  sS  = reinterpret_cast<float*>(sP + QT * SVH);

    const int kstart = max(0, q0 - WIN);
    const int nk     = q0 + QT - kstart;
    const int hq     = h * HD;
    const size_t rowbase = (size_t)(b * TT) * (3 * DD);

    for (int idx = tid; idx < QT * (HD / 8); idx += 256) {
        int q = idx >> 3, d8 = (idx & 7) * 8;
        uint4 v = *reinterpret_cast<const uint4*>(
            &qkv[rowbase + (size_t)(q0 + q) * (3 * DD) + hq + d8]);
        *reinterpret_cast<uint4*>(&sQ[q * SQH + d8]) = v;
    }
    for (int idx = tid; idx < nk * (HD / 8); idx += 256) {
        int kk = idx >> 3, d8 = (idx & 7) * 8;
        uint4 v = *reinterpret_cast<const uint4*>(
            &qkv[rowbase + (size_t)(kstart + kk) * (3 * DD) + DD + hq + d8]);
        *reinterpret_cast<uint4*>(&sK[kk * SQH + d8]) = v;
    }
    for (int idx = tid; idx < HD * SVH / 2; idx += 256)
        reinterpret_cast<uint32_t*>(sVt)[idx] = 0u;
    __syncthreads();
    for (int idx = tid; idx < nk * (HD / 8); idx += 256) {
        int kk = idx >> 3, d8 = (idx & 7) * 8;
        uint4 v = *reinterpret_cast<const uint4*>(
            &qkv[rowbase + (size_t)(kstart + kk) * (3 * DD) + 2 * DD + hq + d8]);
        const __half* hv = reinterpret_cast<const __half*>(&v);
#pragma unroll
        for (int j = 0; j < 8; j++) sVt[(d8 + j) * SVH + kk] = hv[j];
    }
    __syncthreads();

    const uint32_t uQ = smem_u32(sQ);
    const uint32_t uK = smem_u32(sK);
    const uint32_t uP = smem_u32(sP);
    const uint32_t uV = smem_u32(sVt);

    // ---- QK^T: per k16: 1 A-LDSM + 6 B-LDSM, 12 mma ----
    {
        float accS[12][4];
#pragma unroll
        for (int ni = 0; ni < 12; ni++)
#pragma unroll
            for (int q = 0; q < 4; q++) accS[ni][q] = 0.f;

        const int ncol0 = nhalf * 96;
        const uint32_t aoff = uQ + (uint32_t)((mrow + (lane & 7) + ((lane >> 3) & 1) * 8) * SQH
                                              + (lane >> 4) * 8) * 2u;
        const uint32_t boff = uK + (uint32_t)((ncol0 + (lane & 7) + ((lane >> 4) & 1) * 8) * SQH
                                              + ((lane >> 3) & 1) * 8) * 2u;
#pragma unroll
        for (int k16 = 0; k16 < 4; k16++) {
            uint32_t af[4];
            ldsm_x4(af, aoff + k16 * 32);
#pragma unroll
            for (int nip = 0; nip < 6; nip++) {
                uint32_t bq[4];
                ldsm_x4(bq, boff + nip * (16 * SQH * 2) + k16 * 32);
                mma_f16_16x8x16(accS[nip * 2],     af, &bq[0]);
                mma_f16_16x8x16(accS[nip * 2 + 1], af, &bq[2]);
            }
        }

        const float scale = 0.125f;
#pragma unroll
        for (int ni = 0; ni < 12; ni++) {
            const int col = ncol0 + ni * 8 + 2 * tg;
            const int r   = mrow + gid;
            const int i0 = q0 + r, i1 = i0 + 8;
            const int j0 = kstart + col, j1 = j0 + 1;
            sS[(r)     * VSTR + col]     = (j0 <= i0 && j0 >= i0 - WIN) ? accS[ni][0] * scale : -1e30f;
            sS[(r)     * VSTR + col + 1] = (j1 <= i0 && j1 >= i0 - WIN) ? accS[ni][1] * scale : -1e30f;
            sS[(r + 8) * VSTR + col]     = (j0 <= i1 && j0 >= i1 - WIN) ? accS[ni][2] * scale : -1e30f;
            sS[(r + 8) * VSTR + col + 1] = (j1 <= i1 && j1 >= i1 - WIN) ? accS[ni][3] * scale : -1e30f;
        }
    }
    __syncthreads();

    // ---- softmax (fp32 scores -> fp16 probs) ----
    for (int q = wid; q < QT; q += 8) {
        const float* row = &sS[q * VSTR];
        float m = -1e30f;
#pragma unroll
        for (int t = 0; t < 6; t++) m = fmaxf(m, row[lane + t * 32]);
#pragma unroll
        for (int o = 16; o; o >>= 1) m = fmaxf(m, __shfl_xor_sync(0xffffffffu, m, o));
        float s = 0.f;
        float ev[6];
#pragma unroll
        for (int t = 0; t < 6; t++) {
            float e = __expf(row[lane + t * 32] - m);
            ev[t] = e;
            s += e;
        }
#pragma unroll
        for (int o = 16; o; o >>= 1) s += __shfl_xor_sync(0xffffffffu, s, o);
        float inv = 1.f / s;
        __half* prow = &sP[q * SVH];
#pragma unroll
        for (int t = 0; t < 6; t++) prow[lane + t * 32] = __float2half_rn(ev[t] * inv);
    }
    __syncthreads();

    // ---- PV: per k16: 1 A-LDSM + 2 B-LDSM, 4 mma; 12 k16 ----
    {
        float accO[4][4];
#pragma unroll
        for (int ni = 0; ni < 4; ni++)
#pragma unroll
            for (int q = 0; q < 4; q++) accO[ni][q] = 0.f;

        const int dcol0 = nhalf * 32;
        const uint32_t aoff = uP + (uint32_t)((mrow + (lane & 7) + ((lane >> 3) & 1) * 8) * SVH
                                              + (lane >> 4) * 8) * 2u;
        const uint32_t boff = uV + (uint32_t)((dcol0 + (lane & 7) + ((lane >> 4) & 1) * 8) * SVH
                                              + ((lane >> 3) & 1) * 8) * 2u;
#pragma unroll
        for (int k16 = 0; k16 < 12; k16++) {
            uint32_t af[4];
            ldsm_x4(af, aoff + k16 * 32);
#pragma unroll
            for (int nip = 0; nip < 2; nip++) {
                uint32_t bq[4];
                ldsm_x4(bq, boff + nip * (16 * SVH * 2) + k16 * 32);
                mma_f16_16x8x16(accO[nip * 2],     af, &bq[0]);
                mma_f16_16x8x16(accO[nip * 2 + 1], af, &bq[2]);
            }
        }

#pragma unroll
        for (int ni = 0; ni < 4; ni++) {
            const int dc = dcol0 + ni * 8 + 2 * tg;
            const int r  = mrow + gid;
            *reinterpret_cast<__half2*>(&att[(size_t)(b * TT + q0 + r) * DD + hq + dc]) =
                __floats2half2_rn(accO[ni][0], accO[ni][1]);
            *reinterpret_cast<__half2*>(&att[(size_t)(b * TT + q0 + r + 8) * DD + hq + dc]) =
                __floats2half2_rn(accO[ni][2], accO[ni][3]);
        }
    }
}

// ---------------------------------------------------------------------------
extern "C" void kernel_launch(void* const* d_in, const int* in_sizes, int n_in,
                              void* d_out, int out_size) {
    const float* x    = (const float*)d_in[0];
    const float* Wqkv = (const float*)d_in[1];
    const float* Wout = (const float*)d_in[2];
    float* out = (float*)d_out;

    __half *x16, *qkv, *att, *wqkvT, *woutT;
    cudaGetSymbolAddress((void**)&x16, g_x16);
    cudaGetSymbolAddress((void**)&qkv, g_qkv);
    cudaGetSymbolAddress((void**)&att, g_att);
    cudaGetSymbolAddress((void**)&wqkvT, g_wqkvT);
    cudaGetSymbolAddress((void**)&woutT, g_woutT);

    cudaFuncSetAttribute(attn_mma, cudaFuncAttributeMaxDynamicSharedMemorySize, ATT_SMEM);
    cudaFuncSetAttribute(gemm_f16, cudaFuncAttributeMaxDynamicSharedMemorySize, GEMM_SMEM);

    const int M = BB * TT;
    const int xn2 = M * DD / 2;

    f32_to_f16_k<<<(xn2 + 255) / 256, 256>>>(x, x16, xn2);
    transpose_f16_k<<<dim3(3 * DD / 32, DD / 32), dim3(32, 8)>>>(Wqkv, wqkvT, DD, 3 * DD);
    transpose_f16_k<<<dim3(DD / 32, DD / 32), dim3(32, 8)>>>(Wout, woutT, DD, DD);

    gemm_f16<<<dim3(3 * DD / NT, M / MT), GEMM_THREADS, GEMM_SMEM>>>(x16, wqkvT, qkv, 3 * DD, 1);

    attn_mma<<<dim3(TT / QT, HH, BB), 256, ATT_SMEM>>>(qkv, att);

    gemm_f16<<<dim3(DD / NT, M / MT), GEMM_THREADS, GEMM_SMEM>>>(att, woutT, out, DD, 0);
}

// round 13
// speedup vs baseline: 2.4380x; 1.2822x over previous
#include <cuda_runtime.h>
#include <cuda_fp16.h>
#include <cstdint>
#include <cstddef>

// ---------------- problem constants ----------------
#define BB 4
#define TT 2048
#define DD 768
#define HH 12
#define HD 64
#define WIN 128
#define QT 64
#define NKM 192

// ---------------- GEMM tiling (fp16) ----------------
#define MT 128
#define NT 128
#define KC 64
#define KDIM 768
#define NCHUNK (KDIM / KC)
#define GEMM_THREADS 256
#define STRH 72
#define TILE_H (128 * STRH)
#define GEMM_SMEM (2 * 2 * TILE_H * 2)   // 73728 B -> 2 CTAs/SM

// ---------------- attention smem ----------------
#define ATHR 128               // 4 warps
#define SQH 72                 // Q/K half stride (144 B rows: 16B-aligned, word 36 ≡ 4 mod 32)
#define SVH 200                // Vt half stride (400 B rows: 16B-aligned, word 100 ≡ 4 mod 32)
#define ATT_SMEM ((QT * SQH + NKM * SQH + HD * SVH) * 2)   // 62464 B -> 3 CTAs/SM

// ---------------- device scratch ----------------
__device__ __align__(128) __half g_x16 [(size_t)BB * TT * DD];
__device__ __align__(128) __half g_qkv [(size_t)BB * TT * 3 * DD];
__device__ __align__(128) __half g_att [(size_t)BB * TT * DD];
__device__ __align__(128) __half g_wqkvT[(size_t)3 * DD * DD];
__device__ __align__(128) __half g_woutT[(size_t)DD * DD];

// ---------------- helpers ----------------
__device__ __forceinline__ uint32_t smem_u32(const void* p) {
    uint32_t a;
    asm("{ .reg .u64 t; cvta.to.shared.u64 t, %1; cvt.u32.u64 %0, t; }" : "=r"(a) : "l"(p));
    return a;
}
__device__ __forceinline__ void cpa16(uint32_t s, const void* g) {
    asm volatile("cp.async.cg.shared.global [%0], [%1], 16;" :: "r"(s), "l"(g));
}
__device__ __forceinline__ void ldsm_x4(uint32_t* r, uint32_t addr) {
    asm volatile("ldmatrix.sync.aligned.m8n8.x4.shared.b16 {%0,%1,%2,%3}, [%4];"
        : "=r"(r[0]), "=r"(r[1]), "=r"(r[2]), "=r"(r[3]) : "r"(addr));
}
__device__ __forceinline__ void mma_f16_16x8x16(float* d, const uint32_t* a, const uint32_t* b) {
    asm volatile(
        "mma.sync.aligned.m16n8k16.row.col.f32.f16.f16.f32 "
        "{%0,%1,%2,%3}, {%4,%5,%6,%7}, {%8,%9}, {%0,%1,%2,%3};"
        : "+f"(d[0]), "+f"(d[1]), "+f"(d[2]), "+f"(d[3])
        : "r"(a[0]), "r"(a[1]), "r"(a[2]), "r"(a[3]), "r"(b[0]), "r"(b[1]));
}
__device__ __forceinline__ uint32_t pack_h2(float a, float b) {
    __half2 h = __floats2half2_rn(a, b);
    return *reinterpret_cast<uint32_t*>(&h);
}

// ---------------------------------------------------------------------------
__global__ void __launch_bounds__(256) f32_to_f16_k(const float* __restrict__ src,
                                                    __half* __restrict__ dst, int n2) {
    int i = blockIdx.x * 256 + threadIdx.x;
    if (i < n2) {
        float2 v = reinterpret_cast<const float2*>(src)[i];
        reinterpret_cast<__half2*>(dst)[i] = __floats2half2_rn(v.x, v.y);
    }
}

__global__ void __launch_bounds__(256) transpose_f16_k(const float* __restrict__ src,
                                                       __half* __restrict__ dst,
                                                       int R, int C) {
    __shared__ float t[32][33];
    const int c0 = blockIdx.x * 32, r0 = blockIdx.y * 32;
    const int x = threadIdx.x, y = threadIdx.y;
#pragma unroll
    for (int dy = 0; dy < 32; dy += 8)
        t[y + dy][x] = src[(size_t)(r0 + y + dy) * C + c0 + x];
    __syncthreads();
#pragma unroll
    for (int dy = 0; dy < 32; dy += 8)
        dst[(size_t)(c0 + y + dy) * R + r0 + x] = __float2half_rn(t[x][y + dy]);
}

// ---------------------------------------------------------------------------
// fp16 mma.sync GEMM with ldmatrix fragment loads (unchanged from R10).
// ---------------------------------------------------------------------------
__global__ void __launch_bounds__(GEMM_THREADS, 2) gemm_f16(const __half* __restrict__ A,
                                                            const __half* __restrict__ Bt,
                                                            void* __restrict__ Cv,
                                                            int N, int out_half) {
    extern __shared__ __half smh[];
    const uint32_t sAu[2] = { smem_u32(smh),          smem_u32(smh + 2 * TILE_H) };
    const uint32_t sBu[2] = { smem_u32(smh + TILE_H), smem_u32(smh + 3 * TILE_H) };

    const int tid = threadIdx.x;
    const int wid = tid >> 5, lane = tid & 31;
    const int gid = lane >> 2, tg = lane & 3;
    const int wm = (wid & 1) * 64;
    const int wn = (wid >> 1) * 32;
    const int bm = blockIdx.y * MT;
    const int bn = blockIdx.x * NT;

    const uint32_t aoff = (uint32_t)((wm + (lane & 7) + ((lane >> 3) & 1) * 8) * STRH
                                     + (lane >> 4) * 8) * 2u;
    const uint32_t boff = (uint32_t)((wn + (lane & 7) + ((lane >> 4) & 1) * 8) * STRH
                                     + ((lane >> 3) & 1) * 8) * 2u;
    const uint32_t AMI = 16 * STRH * 2;
    const uint32_t BNI = 16 * STRH * 2;

    int lrow[4], lc8[4];
    const __half *gA[4], *gB[4];
#pragma unroll
    for (int i = 0; i < 4; i++) {
        int f = tid + i * 256;
        lrow[i] = f >> 3;
        lc8[i]  = f & 7;
        gA[i] = A  + (size_t)(bm + lrow[i]) * KDIM + lc8[i] * 8;
        gB[i] = Bt + (size_t)(bn + lrow[i]) * KDIM + lc8[i] * 8;
    }

    auto load_chunk = [&](int kc, int s) {
        const int ko = kc * KC;
#pragma unroll
        for (int i = 0; i < 4; i++) {
            uint32_t off = (uint32_t)(lrow[i] * STRH + lc8[i] * 8) * 2u;
            cpa16(sAu[s] + off, gA[i] + ko);
            cpa16(sBu[s] + off, gB[i] + ko);
        }
        asm volatile("cp.async.commit_group;" ::: "memory");
    };

    float acc[4][4][4];
#pragma unroll
    for (int mi = 0; mi < 4; mi++)
#pragma unroll
        for (int ni = 0; ni < 4; ni++)
#pragma unroll
            for (int q = 0; q < 4; q++) acc[mi][ni][q] = 0.f;

    load_chunk(0, 0);

    for (int c = 0; c < NCHUNK; ++c) {
        const int s = c & 1;
        if (c + 1 < NCHUNK) {
            load_chunk(c + 1, s ^ 1);
            asm volatile("cp.async.wait_group 1;" ::: "memory");
        } else {
            asm volatile("cp.async.wait_group 0;" ::: "memory");
        }
        __syncthreads();

        const uint32_t abase = sAu[s] + aoff;
        const uint32_t bbase = sBu[s] + boff;
#pragma unroll
        for (int k16 = 0; k16 < 4; k16++) {
            uint32_t af[4][4], bq[2][4];
#pragma unroll
            for (int mi = 0; mi < 4; mi++)
                ldsm_x4(af[mi], abase + mi * AMI + k16 * 32);
#pragma unroll
            for (int nip = 0; nip < 2; nip++)
                ldsm_x4(bq[nip], bbase + nip * BNI + k16 * 32);
#pragma unroll
            for (int mi = 0; mi < 4; mi++)
#pragma unroll
                for (int ni = 0; ni < 4; ni++)
                    mma_f16_16x8x16(acc[mi][ni], af[mi], &bq[ni >> 1][(ni & 1) * 2]);
        }
        __syncthreads();
    }

#pragma unroll
    for (int mi = 0; mi < 4; mi++) {
        const int r0 = bm + wm + mi * 16 + gid;
#pragma unroll
        for (int ni = 0; ni < 4; ni++) {
            const int c0 = bn + wn + ni * 8 + tg * 2;
            if (out_half) {
                __half* Ch = (__half*)Cv;
                *reinterpret_cast<__half2*>(&Ch[(size_t)r0 * N + c0]) =
                    __floats2half2_rn(acc[mi][ni][0], acc[mi][ni][1]);
                *reinterpret_cast<__half2*>(&Ch[(size_t)(r0 + 8) * N + c0]) =
                    __floats2half2_rn(acc[mi][ni][2], acc[mi][ni][3]);
            } else {
                float* Cf = (float*)Cv;
                *reinterpret_cast<float2*>(&Cf[(size_t)r0 * N + c0]) =
                    make_float2(acc[mi][ni][0], acc[mi][ni][1]);
                *reinterpret_cast<float2*>(&Cf[(size_t)(r0 + 8) * N + c0]) =
                    make_float2(acc[mi][ni][2], acc[mi][ni][3]);
            }
        }
    }
}

// ---------------------------------------------------------------------------
// FA2-style attention: 4 warps, warp = 16 rows x full 192-key window,
// register-resident softmax, P never hits smem.
// ---------------------------------------------------------------------------
__global__ void __launch_bounds__(ATHR, 3) attn_mma(const __half* __restrict__ qkv,
                                                    __half* __restrict__ att) {
    const int q0 = blockIdx.x * QT;
    const int h  = blockIdx.y;
    const int b  = blockIdx.z;
    const int tid = threadIdx.x;
    const int wid = tid >> 5, lane = tid & 31;
    const int gid = lane >> 2, tg = lane & 3;
    const int mrow = wid * 16;

    extern __shared__ __half smh[];
    __half* sQ  = smh;                       // [64][SQH]
    __half* sK  = sQ  + QT  * SQH;           // [192][SQH]
    __half* sVt = sK  + NKM * SQH;           // [64][SVH]

    const int kstart = max(0, q0 - WIN);
    const int nk     = q0 + QT - kstart;     // 64 or 192
    const int hq     = h * HD;
    const size_t rowbase = (size_t)(b * TT) * (3 * DD);

    for (int idx = tid; idx < QT * (HD / 8); idx += ATHR) {
        int q = idx >> 3, d8 = (idx & 7) * 8;
        uint4 v = *reinterpret_cast<const uint4*>(
            &qkv[rowbase + (size_t)(q0 + q) * (3 * DD) + hq + d8]);
        *reinterpret_cast<uint4*>(&sQ[q * SQH + d8]) = v;
    }
    for (int idx = tid; idx < nk * (HD / 8); idx += ATHR) {
        int kk = idx >> 3, d8 = (idx & 7) * 8;
        uint4 v = *reinterpret_cast<const uint4*>(
            &qkv[rowbase + (size_t)(kstart + kk) * (3 * DD) + DD + hq + d8]);
        *reinterpret_cast<uint4*>(&sK[kk * SQH + d8]) = v;
    }
    for (int idx = tid; idx < HD * SVH / 2; idx += ATHR)
        reinterpret_cast<uint32_t*>(sVt)[idx] = 0u;
    __syncthreads();
    for (int idx = tid; idx < nk * (HD / 8); idx += ATHR) {
        int kk = idx >> 3, d8 = (idx & 7) * 8;
        uint4 v = *reinterpret_cast<const uint4*>(
            &qkv[rowbase + (size_t)(kstart + kk) * (3 * DD) + 2 * DD + hq + d8]);
        const __half* hv = reinterpret_cast<const __half*>(&v);
#pragma unroll
        for (int j = 0; j < 8; j++) sVt[(d8 + j) * SVH + kk] = hv[j];
    }
    __syncthreads();

    const uint32_t uQ = smem_u32(sQ);
    const uint32_t uK = smem_u32(sK);
    const uint32_t uV = smem_u32(sVt);

    // ---- QK^T: 24 n-frags (192 cols) x 4 k16 steps ----
    float accS[24][4];
#pragma unroll
    for (int ni = 0; ni < 24; ni++)
#pragma unroll
        for (int q = 0; q < 4; q++) accS[ni][q] = 0.f;

    {
        const uint32_t aoff = uQ + (uint32_t)((mrow + (lane & 7) + ((lane >> 3) & 1) * 8) * SQH
                                              + (lane >> 4) * 8) * 2u;
        const uint32_t boff = uK + (uint32_t)(((lane & 7) + ((lane >> 4) & 1) * 8) * SQH
                                              + ((lane >> 3) & 1) * 8) * 2u;
#pragma unroll
        for (int k16 = 0; k16 < 4; k16++) {
            uint32_t af[4];
            ldsm_x4(af, aoff + k16 * 32);
#pragma unroll
            for (int nip = 0; nip < 12; nip++) {
                uint32_t bq[4];
                ldsm_x4(bq, boff + nip * (16 * SQH * 2) + k16 * 32);
                mma_f16_16x8x16(accS[nip * 2],     af, &bq[0]);
                mma_f16_16x8x16(accS[nip * 2 + 1], af, &bq[2]);
            }
        }
    }

    // ---- mask + scale (in registers) ----
    const int i0 = q0 + mrow + gid, i1 = i0 + 8;
    const float scale = 0.125f;
#pragma unroll
    for (int ni = 0; ni < 24; ni++) {
        const int j0 = kstart + ni * 8 + 2 * tg, j1 = j0 + 1;
        accS[ni][0] = (j0 <= i0 && j0 >= i0 - WIN) ? accS[ni][0] * scale : -1e30f;
        accS[ni][1] = (j1 <= i0 && j1 >= i0 - WIN) ? accS[ni][1] * scale : -1e30f;
        accS[ni][2] = (j0 <= i1 && j0 >= i1 - WIN) ? accS[ni][2] * scale : -1e30f;
        accS[ni][3] = (j1 <= i1 && j1 >= i1 - WIN) ? accS[ni][3] * scale : -1e30f;
    }

    // ---- row max (row lives in a 4-lane group: shuffle xor 1,2) ----
    float m0 = -1e30f, m1 = -1e30f;
#pragma unroll
    for (int ni = 0; ni < 24; ni++) {
        m0 = fmaxf(m0, fmaxf(accS[ni][0], accS[ni][1]));
        m1 = fmaxf(m1, fmaxf(accS[ni][2], accS[ni][3]));
    }
    m0 = fmaxf(m0, __shfl_xor_sync(0xffffffffu, m0, 1));
    m0 = fmaxf(m0, __shfl_xor_sync(0xffffffffu, m0, 2));
    m1 = fmaxf(m1, __shfl_xor_sync(0xffffffffu, m1, 1));
    m1 = fmaxf(m1, __shfl_xor_sync(0xffffffffu, m1, 2));

    // ---- exp + row sum ----
    float s0 = 0.f, s1 = 0.f;
#pragma unroll
    for (int ni = 0; ni < 24; ni++) {
        accS[ni][0] = __expf(accS[ni][0] - m0);
        accS[ni][1] = __expf(accS[ni][1] - m0);
        accS[ni][2] = __expf(accS[ni][2] - m1);
        accS[ni][3] = __expf(accS[ni][3] - m1);
        s0 += accS[ni][0] + accS[ni][1];
        s1 += accS[ni][2] + accS[ni][3];
    }
    s0 += __shfl_xor_sync(0xffffffffu, s0, 1);
    s0 += __shfl_xor_sync(0xffffffffu, s0, 2);
    s1 += __shfl_xor_sync(0xffffffffu, s1, 1);
    s1 += __shfl_xor_sync(0xffffffffu, s1, 2);
    const float inv0 = 1.f / s0, inv1 = 1.f / s1;

    // ---- pack P into A-fragments (C-layout == A-layout identity) ----
    uint32_t pf[24], pg[24];
#pragma unroll
    for (int ni = 0; ni < 24; ni++) {
        pf[ni] = pack_h2(accS[ni][0] * inv0, accS[ni][1] * inv0);
        pg[ni] = pack_h2(accS[ni][2] * inv1, accS[ni][3] * inv1);
    }

    // ---- PV: 8 n-frags (64 dims) x 12 k16 steps, A from registers ----
    float accO[8][4];
#pragma unroll
    for (int ni = 0; ni < 8; ni++)
#pragma unroll
        for (int q = 0; q < 4; q++) accO[ni][q] = 0.f;

    {
        const uint32_t boff = uV + (uint32_t)(((lane & 7) + ((lane >> 4) & 1) * 8) * SVH
                                              + ((lane >> 3) & 1) * 8) * 2u;
#pragma unroll
        for (int k16 = 0; k16 < 12; k16++) {
            uint32_t af[4] = { pf[2 * k16], pg[2 * k16], pf[2 * k16 + 1], pg[2 * k16 + 1] };
#pragma unroll
            for (int nip = 0; nip < 4; nip++) {
                uint32_t bq[4];
                ldsm_x4(bq, boff + nip * (16 * SVH * 2) + k16 * 32);
                mma_f16_16x8x16(accO[nip * 2],     af, &bq[0]);
                mma_f16_16x8x16(accO[nip * 2 + 1], af, &bq[2]);
            }
        }
    }

#pragma unroll
    for (int ni = 0; ni < 8; ni++) {
        const int dc = ni * 8 + 2 * tg;
        const int r  = mrow + gid;
        *reinterpret_cast<__half2*>(&att[(size_t)(b * TT + q0 + r) * DD + hq + dc]) =
            __floats2half2_rn(accO[ni][0], accO[ni][1]);
        *reinterpret_cast<__half2*>(&att[(size_t)(b * TT + q0 + r + 8) * DD + hq + dc]) =
            __floats2half2_rn(accO[ni][2], accO[ni][3]);
    }
}

// ---------------------------------------------------------------------------
extern "C" void kernel_launch(void* const* d_in, const int* in_sizes, int n_in,
                              void* d_out, int out_size) {
    const float* x    = (const float*)d_in[0];
    const float* Wqkv = (const float*)d_in[1];
    const float* Wout = (const float*)d_in[2];
    float* out = (float*)d_out;

    __half *x16, *qkv, *att, *wqkvT, *woutT;
    cudaGetSymbolAddress((void**)&x16, g_x16);
    cudaGetSymbolAddress((void**)&qkv, g_qkv);
    cudaGetSymbolAddress((void**)&att, g_att);
    cudaGetSymbolAddress((void**)&wqkvT, g_wqkvT);
    cudaGetSymbolAddress((void**)&woutT, g_woutT);

    cudaFuncSetAttribute(attn_mma, cudaFuncAttributeMaxDynamicSharedMemorySize, ATT_SMEM);
    cudaFuncSetAttribute(gemm_f16, cudaFuncAttributeMaxDynamicSharedMemorySize, GEMM_SMEM);

    const int M = BB * TT;
    const int xn2 = M * DD / 2;

    f32_to_f16_k<<<(xn2 + 255) / 256, 256>>>(x, x16, xn2);
    transpose_f16_k<<<dim3(3 * DD / 32, DD / 32), dim3(32, 8)>>>(Wqkv, wqkvT, DD, 3 * DD);
    transpose_f16_k<<<dim3(DD / 32, DD / 32), dim3(32, 8)>>>(Wout, woutT, DD, DD);

    gemm_f16<<<dim3(3 * DD / NT, M / MT), GEMM_THREADS, GEMM_SMEM>>>(x16, wqkvT, qkv, 3 * DD, 1);

    attn_mma<<<dim3(TT / QT, HH, BB), ATHR, ATT_SMEM>>>(qkv, att);

    gemm_f16<<<dim3(DD / NT, M / MT), GEMM_THREADS, GEMM_SMEM>>>(att, woutT, out, DD, 0);
}

// round 14
// speedup vs baseline: 2.7720x; 1.1370x over previous
#include <cuda_runtime.h>
#include <cuda_fp16.h>
#include <cstdint>
#include <cstddef>

// ---------------- problem constants ----------------
#define BB 4
#define TT 2048
#define DD 768
#define HH 12
#define HD 64
#define WIN 128
#define QT 64
#define NKM 192

// ---------------- GEMM tiling (fp16) ----------------
#define MT 128
#define NT 128
#define KC 64
#define KDIM 768
#define NCHUNK (KDIM / KC)
#define GEMM_THREADS 256
#define STRH 72
#define TILE_H (128 * STRH)
#define GEMM_SMEM (2 * 2 * TILE_H * 2)   // 73728 B -> 2 CTAs/SM

// ---------------- attention smem ----------------
#define ATHR 128               // 4 warps
#define SQH 72                 // Q/K/V half stride (144 B rows: 16B-aligned, word 36 ≡ 4 mod 32)
#define ATT_SMEM ((QT * SQH + NKM * SQH + NKM * SQH) * 2)   // 64512 B -> 3 CTAs/SM

// ---------------- fused preprocessing grid sections ----------------
#define CONV_N2    ((BB * TT * DD) / 2)          // 3145728 half2 pairs
#define CONV_BLKS  (CONV_N2 / 256)               // 12288
#define T1_BX      (3 * DD / 32)                 // 72
#define T1_BLKS    (T1_BX * (DD / 32))           // 1728
#define T2_BX      (DD / 32)                     // 24
#define T2_BLKS    (T2_BX * (DD / 32))           // 576
#define PRE_BLKS   (CONV_BLKS + T1_BLKS + T2_BLKS)

// ---------------- device scratch ----------------
__device__ __align__(128) __half g_x16 [(size_t)BB * TT * DD];
__device__ __align__(128) __half g_qkv [(size_t)BB * TT * 3 * DD];
__device__ __align__(128) __half g_att [(size_t)BB * TT * DD];
__device__ __align__(128) __half g_wqkvT[(size_t)3 * DD * DD];
__device__ __align__(128) __half g_woutT[(size_t)DD * DD];

// ---------------- helpers ----------------
__device__ __forceinline__ uint32_t smem_u32(const void* p) {
    uint32_t a;
    asm("{ .reg .u64 t; cvta.to.shared.u64 t, %1; cvt.u32.u64 %0, t; }" : "=r"(a) : "l"(p));
    return a;
}
__device__ __forceinline__ void cpa16(uint32_t s, const void* g) {
    asm volatile("cp.async.cg.shared.global [%0], [%1], 16;" :: "r"(s), "l"(g));
}
__device__ __forceinline__ void ldsm_x4(uint32_t* r, uint32_t addr) {
    asm volatile("ldmatrix.sync.aligned.m8n8.x4.shared.b16 {%0,%1,%2,%3}, [%4];"
        : "=r"(r[0]), "=r"(r[1]), "=r"(r[2]), "=r"(r[3]) : "r"(addr));
}
__device__ __forceinline__ void ldsm_x4_t(uint32_t* r, uint32_t addr) {
    asm volatile("ldmatrix.sync.aligned.m8n8.x4.trans.shared.b16 {%0,%1,%2,%3}, [%4];"
        : "=r"(r[0]), "=r"(r[1]), "=r"(r[2]), "=r"(r[3]) : "r"(addr));
}
__device__ __forceinline__ void mma_f16_16x8x16(float* d, const uint32_t* a, const uint32_t* b) {
    asm volatile(
        "mma.sync.aligned.m16n8k16.row.col.f32.f16.f16.f32 "
        "{%0,%1,%2,%3}, {%4,%5,%6,%7}, {%8,%9}, {%0,%1,%2,%3};"
        : "+f"(d[0]), "+f"(d[1]), "+f"(d[2]), "+f"(d[3])
        : "r"(a[0]), "r"(a[1]), "r"(a[2]), "r"(a[3]), "r"(b[0]), "r"(b[1]));
}
__device__ __forceinline__ uint32_t pack_h2(float a, float b) {
    __half2 h = __floats2half2_rn(a, b);
    return *reinterpret_cast<uint32_t*>(&h);
}

// ---------------------------------------------------------------------------
// Fused preprocessing: x f32->f16 | Wqkv transpose->f16 | Wout transpose->f16
// ---------------------------------------------------------------------------
__global__ void __launch_bounds__(256) pre_k(const float* __restrict__ x,
                                             __half* __restrict__ x16,
                                             const float* __restrict__ Wqkv,
                                             __half* __restrict__ wqkvT,
                                             const float* __restrict__ Wout,
                                             __half* __restrict__ woutT) {
    const int bid = blockIdx.x;
    const int tid = threadIdx.x;
    if (bid < CONV_BLKS) {
        int i = bid * 256 + tid;
        float2 v = reinterpret_cast<const float2*>(x)[i];
        reinterpret_cast<__half2*>(x16)[i] = __floats2half2_rn(v.x, v.y);
        return;
    }
    __shared__ float t[32][33];
    const int xx = tid & 31, yy = tid >> 5;
    const float* src;
    __half* dst;
    int R, C, c0, r0;
    if (bid < CONV_BLKS + T1_BLKS) {
        int b = bid - CONV_BLKS;
        src = Wqkv; dst = wqkvT; R = DD; C = 3 * DD;
        c0 = (b % T1_BX) * 32; r0 = (b / T1_BX) * 32;
    } else {
        int b = bid - CONV_BLKS - T1_BLKS;
        src = Wout; dst = woutT; R = DD; C = DD;
        c0 = (b % T2_BX) * 32; r0 = (b / T2_BX) * 32;
    }
#pragma unroll
    for (int dy = 0; dy < 32; dy += 8)
        t[yy + dy][xx] = src[(size_t)(r0 + yy + dy) * C + c0 + xx];
    __syncthreads();
#pragma unroll
    for (int dy = 0; dy < 32; dy += 8)
        dst[(size_t)(c0 + yy + dy) * R + r0 + xx] = __float2half_rn(t[xx][yy + dy]);
}

// ---------------------------------------------------------------------------
// fp16 mma.sync GEMM with ldmatrix fragment loads (unchanged from R13).
// ---------------------------------------------------------------------------
__global__ void __launch_bounds__(GEMM_THREADS, 2) gemm_f16(const __half* __restrict__ A,
                                                            const __half* __restrict__ Bt,
                                                            void* __restrict__ Cv,
                                                            int N, int out_half) {
    extern __shared__ __half smh[];
    const uint32_t sAu[2] = { smem_u32(smh),          smem_u32(smh + 2 * TILE_H) };
    const uint32_t sBu[2] = { smem_u32(smh + TILE_H), smem_u32(smh + 3 * TILE_H) };

    const int tid = threadIdx.x;
    const int wid = tid >> 5, lane = tid & 31;
    const int gid = lane >> 2, tg = lane & 3;
    const int wm = (wid & 1) * 64;
    const int wn = (wid >> 1) * 32;
    const int bm = blockIdx.y * MT;
    const int bn = blockIdx.x * NT;

    const uint32_t aoff = (uint32_t)((wm + (lane & 7) + ((lane >> 3) & 1) * 8) * STRH
                                     + (lane >> 4) * 8) * 2u;
    const uint32_t boff = (uint32_t)((wn + (lane & 7) + ((lane >> 4) & 1) * 8) * STRH
                                     + ((lane >> 3) & 1) * 8) * 2u;
    const uint32_t AMI = 16 * STRH * 2;
    const uint32_t BNI = 16 * STRH * 2;

    int lrow[4], lc8[4];
    const __half *gA[4], *gB[4];
#pragma unroll
    for (int i = 0; i < 4; i++) {
        int f = tid + i * 256;
        lrow[i] = f >> 3;
        lc8[i]  = f & 7;
        gA[i] = A  + (size_t)(bm + lrow[i]) * KDIM + lc8[i] * 8;
        gB[i] = Bt + (size_t)(bn + lrow[i]) * KDIM + lc8[i] * 8;
    }

    auto load_chunk = [&](int kc, int s) {
        const int ko = kc * KC;
#pragma unroll
        for (int i = 0; i < 4; i++) {
            uint32_t off = (uint32_t)(lrow[i] * STRH + lc8[i] * 8) * 2u;
            cpa16(sAu[s] + off, gA[i] + ko);
            cpa16(sBu[s] + off, gB[i] + ko);
        }
        asm volatile("cp.async.commit_group;" ::: "memory");
    };

    float acc[4][4][4];
#pragma unroll
    for (int mi = 0; mi < 4; mi++)
#pragma unroll
        for (int ni = 0; ni < 4; ni++)
#pragma unroll
            for (int q = 0; q < 4; q++) acc[mi][ni][q] = 0.f;

    load_chunk(0, 0);

    for (int c = 0; c < NCHUNK; ++c) {
        const int s = c & 1;
        if (c + 1 < NCHUNK) {
            load_chunk(c + 1, s ^ 1);
            asm volatile("cp.async.wait_group 1;" ::: "memory");
        } else {
            asm volatile("cp.async.wait_group 0;" ::: "memory");
        }
        __syncthreads();

        const uint32_t abase = sAu[s] + aoff;
        const uint32_t bbase = sBu[s] + boff;
#pragma unroll
        for (int k16 = 0; k16 < 4; k16++) {
            uint32_t af[4][4], bq[2][4];
#pragma unroll
            for (int mi = 0; mi < 4; mi++)
                ldsm_x4(af[mi], abase + mi * AMI + k16 * 32);
#pragma unroll
            for (int nip = 0; nip < 2; nip++)
                ldsm_x4(bq[nip], bbase + nip * BNI + k16 * 32);
#pragma unroll
            for (int mi = 0; mi < 4; mi++)
#pragma unroll
                for (int ni = 0; ni < 4; ni++)
                    mma_f16_16x8x16(acc[mi][ni], af[mi], &bq[ni >> 1][(ni & 1) * 2]);
        }
        __syncthreads();
    }

#pragma unroll
    for (int mi = 0; mi < 4; mi++) {
        const int r0 = bm + wm + mi * 16 + gid;
#pragma unroll
        for (int ni = 0; ni < 4; ni++) {
            const int c0 = bn + wn + ni * 8 + tg * 2;
            if (out_half) {
                __half* Ch = (__half*)Cv;
                *reinterpret_cast<__half2*>(&Ch[(size_t)r0 * N + c0]) =
                    __floats2half2_rn(acc[mi][ni][0], acc[mi][ni][1]);
                *reinterpret_cast<__half2*>(&Ch[(size_t)(r0 + 8) * N + c0]) =
                    __floats2half2_rn(acc[mi][ni][2], acc[mi][ni][3]);
            } else {
                float* Cf = (float*)Cv;
                *reinterpret_cast<float2*>(&Cf[(size_t)r0 * N + c0]) =
                    make_float2(acc[mi][ni][0], acc[mi][ni][1]);
                *reinterpret_cast<float2*>(&Cf[(size_t)(r0 + 8) * N + c0]) =
                    make_float2(acc[mi][ni][2], acc[mi][ni][3]);
            }
        }
    }
}

// ---------------------------------------------------------------------------
// FA2-style attention: register-resident softmax, V loaded row-major
// (coalesced) and transposed on the fly via ldmatrix.trans.
// ---------------------------------------------------------------------------
__global__ void __launch_bounds__(ATHR, 3) attn_mma(const __half* __restrict__ qkv,
                                                    __half* __restrict__ att) {
    const int q0 = blockIdx.x * QT;
    const int h  = blockIdx.y;
    const int b  = blockIdx.z;
    const int tid = threadIdx.x;
    const int wid = tid >> 5, lane = tid & 31;
    const int gid = lane >> 2, tg = lane & 3;
    const int mrow = wid * 16;

    extern __shared__ __half smh[];
    __half* sQ = smh;                        // [64][SQH]
    __half* sK = sQ + QT  * SQH;             // [192][SQH]
    __half* sV = sK + NKM * SQH;             // [192][SQH]  row-major [kk][d]

    const int kstart = max(0, q0 - WIN);
    const int nk     = q0 + QT - kstart;     // 64, 128 or 192
    const int hq     = h * HD;
    const size_t rowbase = (size_t)(b * TT) * (3 * DD);

    for (int idx = tid; idx < QT * (HD / 8); idx += ATHR) {
        int q = idx >> 3, d8 = (idx & 7) * 8;
        uint4 v = *reinterpret_cast<const uint4*>(
            &qkv[rowbase + (size_t)(q0 + q) * (3 * DD) + hq + d8]);
        *reinterpret_cast<uint4*>(&sQ[q * SQH + d8]) = v;
    }
    for (int idx = tid; idx < nk * (HD / 8); idx += ATHR) {
        int kk = idx >> 3, d8 = (idx & 7) * 8;
        uint4 v = *reinterpret_cast<const uint4*>(
            &qkv[rowbase + (size_t)(kstart + kk) * (3 * DD) + DD + hq + d8]);
        *reinterpret_cast<uint4*>(&sK[kk * SQH + d8]) = v;
        uint4 w = *reinterpret_cast<const uint4*>(
            &qkv[rowbase + (size_t)(kstart + kk) * (3 * DD) + 2 * DD + hq + d8]);
        *reinterpret_cast<uint4*>(&sV[kk * SQH + d8]) = w;
    }
    // Zero V rows [nk, NKM): P is exactly 0 there, but 0 * NaN-garbage = NaN.
    for (int idx = nk * (HD / 8) + tid; idx < NKM * (HD / 8); idx += ATHR) {
        int kk = idx >> 3, d8 = (idx & 7) * 8;
        *reinterpret_cast<uint4*>(&sV[kk * SQH + d8]) = make_uint4(0u, 0u, 0u, 0u);
    }
    __syncthreads();

    const uint32_t uQ = smem_u32(sQ);
    const uint32_t uK = smem_u32(sK);
    const uint32_t uV = smem_u32(sV);

    // ---- QK^T: 24 n-frags (192 cols) x 4 k16 steps ----
    float accS[24][4];
#pragma unroll
    for (int ni = 0; ni < 24; ni++)
#pragma unroll
        for (int q = 0; q < 4; q++) accS[ni][q] = 0.f;

    {
        const uint32_t aoff = uQ + (uint32_t)((mrow + (lane & 7) + ((lane >> 3) & 1) * 8) * SQH
                                              + (lane >> 4) * 8) * 2u;
        const uint32_t boff = uK + (uint32_t)(((lane & 7) + ((lane >> 4) & 1) * 8) * SQH
                                              + ((lane >> 3) & 1) * 8) * 2u;
#pragma unroll
        for (int k16 = 0; k16 < 4; k16++) {
            uint32_t af[4];
            ldsm_x4(af, aoff + k16 * 32);
#pragma unroll
            for (int nip = 0; nip < 12; nip++) {
                uint32_t bq[4];
                ldsm_x4(bq, boff + nip * (16 * SQH * 2) + k16 * 32);
                mma_f16_16x8x16(accS[nip * 2],     af, &bq[0]);
                mma_f16_16x8x16(accS[nip * 2 + 1], af, &bq[2]);
            }
        }
    }

    // ---- mask + scale (in registers) ----
    const int i0 = q0 + mrow + gid, i1 = i0 + 8;
    const float scale = 0.125f;
#pragma unroll
    for (int ni = 0; ni < 24; ni++) {
        const int j0 = kstart + ni * 8 + 2 * tg, j1 = j0 + 1;
        accS[ni][0] = (j0 <= i0 && j0 >= i0 - WIN) ? accS[ni][0] * scale : -1e30f;
        accS[ni][1] = (j1 <= i0 && j1 >= i0 - WIN) ? accS[ni][1] * scale : -1e30f;
        accS[ni][2] = (j0 <= i1 && j0 >= i1 - WIN) ? accS[ni][2] * scale : -1e30f;
        accS[ni][3] = (j1 <= i1 && j1 >= i1 - WIN) ? accS[ni][3] * scale : -1e30f;
    }

    // ---- row max (row lives in a 4-lane group: shuffle xor 1,2) ----
    float m0 = -1e30f, m1 = -1e30f;
#pragma unroll
    for (int ni = 0; ni < 24; ni++) {
        m0 = fmaxf(m0, fmaxf(accS[ni][0], accS[ni][1]));
        m1 = fmaxf(m1, fmaxf(accS[ni][2], accS[ni][3]));
    }
    m0 = fmaxf(m0, __shfl_xor_sync(0xffffffffu, m0, 1));
    m0 = fmaxf(m0, __shfl_xor_sync(0xffffffffu, m0, 2));
    m1 = fmaxf(m1, __shfl_xor_sync(0xffffffffu, m1, 1));
    m1 = fmaxf(m1, __shfl_xor_sync(0xffffffffu, m1, 2));

    // ---- exp + row sum ----
    float s0 = 0.f, s1 = 0.f;
#pragma unroll
    for (int ni = 0; ni < 24; ni++) {
        accS[ni][0] = __expf(accS[ni][0] - m0);
        accS[ni][1] = __expf(accS[ni][1] - m0);
        accS[ni][2] = __expf(accS[ni][2] - m1);
        accS[ni][3] = __expf(accS[ni][3] - m1);
        s0 += accS[ni][0] + accS[ni][1];
        s1 += accS[ni][2] + accS[ni][3];
    }
    s0 += __shfl_xor_sync(0xffffffffu, s0, 1);
    s0 += __shfl_xor_sync(0xffffffffu, s0, 2);
    s1 += __shfl_xor_sync(0xffffffffu, s1, 1);
    s1 += __shfl_xor_sync(0xffffffffu, s1, 2);
    const float inv0 = 1.f / s0, inv1 = 1.f / s1;

    // ---- pack P into A-fragments (C-layout == A-layout identity) ----
    uint32_t pf[24], pg[24];
#pragma unroll
    for (int ni = 0; ni < 24; ni++) {
        pf[ni] = pack_h2(accS[ni][0] * inv0, accS[ni][1] * inv0);
        pg[ni] = pack_h2(accS[ni][2] * inv1, accS[ni][3] * inv1);
    }

    // ---- PV: B-frags via ldmatrix.trans of row-major V ----
    float accO[8][4];
#pragma unroll
    for (int ni = 0; ni < 8; ni++)
#pragma unroll
        for (int q = 0; q < 4; q++) accO[ni][q] = 0.f;

    {
        // trans-x4 lane addressing: lanes 0-7 rows kk0-7 @ d0 (matrix0 -> [d0-7][kk0-7]),
        // lanes 8-15 rows kk8-15 @ d0, lanes 16-23 rows kk0-7 @ d8, lanes 24-31 rows kk8-15 @ d8.
        const uint32_t vbase = uV + (uint32_t)(((lane & 7) + ((lane >> 3) & 1) * 8) * SQH
                                               + ((lane >> 4) & 1) * 8) * 2u;
#pragma unroll
        for (int k16 = 0; k16 < 12; k16++) {
            uint32_t af[4] = { pf[2 * k16], pg[2 * k16], pf[2 * k16 + 1], pg[2 * k16 + 1] };
#pragma unroll
            for (int dp = 0; dp < 4; dp++) {   // 16 d per trans-x4
                uint32_t bq[4];
                ldsm_x4_t(bq, vbase + (uint32_t)(k16 * 16 * SQH + dp * 16) * 2u);
                mma_f16_16x8x16(accO[dp * 2],     af, &bq[0]);   // d 0-7 of pair
                mma_f16_16x8x16(accO[dp * 2 + 1], af, &bq[2]);   // d 8-15
            }
        }
    }

#pragma unroll
    for (int ni = 0; ni < 8; ni++) {
        const int dc = ni * 8 + 2 * tg;
        const int r  = mrow + gid;
        *reinterpret_cast<__half2*>(&att[(size_t)(b * TT + q0 + r) * DD + hq + dc]) =
            __floats2half2_rn(accO[ni][0], accO[ni][1]);
        *reinterpret_cast<__half2*>(&att[(size_t)(b * TT + q0 + r + 8) * DD + hq + dc]) =
            __floats2half2_rn(accO[ni][2], accO[ni][3]);
    }
}

// ---------------------------------------------------------------------------
extern "C" void kernel_launch(void* const* d_in, const int* in_sizes, int n_in,
                              void* d_out, int out_size) {
    const float* x    = (const float*)d_in[0];
    const float* Wqkv = (const float*)d_in[1];
    const float* Wout = (const float*)d_in[2];
    float* out = (float*)d_out;

    __half *x16, *qkv, *att, *wqkvT, *woutT;
    cudaGetSymbolAddress((void**)&x16, g_x16);
    cudaGetSymbolAddress((void**)&qkv, g_qkv);
    cudaGetSymbolAddress((void**)&att, g_att);
    cudaGetSymbolAddress((void**)&wqkvT, g_wqkvT);
    cudaGetSymbolAddress((void**)&woutT, g_woutT);

    cudaFuncSetAttribute(attn_mma, cudaFuncAttributeMaxDynamicSharedMemorySize, ATT_SMEM);
    cudaFuncSetAttribute(gemm_f16, cudaFuncAttributeMaxDynamicSharedMemorySize, GEMM_SMEM);

    const int M = BB * TT;

    // 0) fused preprocessing (convert x + transpose both weights)
    pre_k<<<PRE_BLKS, 256>>>(x, x16, Wqkv, wqkvT, Wout, woutT);

    // 1) QKV projection
    gemm_f16<<<dim3(3 * DD / NT, M / MT), GEMM_THREADS, GEMM_SMEM>>>(x16, wqkvT, qkv, 3 * DD, 1);

    // 2) attention
    attn_mma<<<dim3(TT / QT, HH, BB), ATHR, ATT_SMEM>>>(qkv, att);

    // 3) output projection
    gemm_f16<<<dim3(DD / NT, M / MT), GEMM_THREADS, GEMM_SMEM>>>(att, woutT, out, DD, 0);
}